// round 5
// baseline (speedup 1.0000x reference)
#include <cuda_runtime.h>

#define S_LEN   2048
#define NHEADS  16
#define HD      64
#define BATCH   2
#define HID     1024

// Scratch: Q and V in head-major layout [B, H, S, 64]
__device__ float g_q[BATCH * NHEADS * S_LEN * HD];
__device__ float g_v[BATCH * NHEADS * S_LEN * HD];

// ---------------------------------------------------------------------------
// Kernel A: fused Q/V projection GEMM (unchanged: at fp32 FFMA issue floor).
// Y = X[4096,1024] @ W[1024,1024] + b, written to head-major scratch.
// ---------------------------------------------------------------------------
__global__ __launch_bounds__(256)
void qv_gemm(const float* __restrict__ X,
             const float* __restrict__ Wq, const float* __restrict__ bq,
             const float* __restrict__ Wv, const float* __restrict__ bv) {
    __shared__ float As[16 * 128];   // [k][m] (transposed on store)
    __shared__ float Bs[16 * 128];   // [k][n]

    const float* W    = blockIdx.z ? Wv : Wq;
    const float* bias = blockIdx.z ? bv : bq;
    float*       out  = blockIdx.z ? g_v : g_q;

    const int tid = threadIdx.x;
    const int bx = blockIdx.x, by = blockIdx.y;
    const int tx = tid & 15, ty = tid >> 4;

    const int arow = tid >> 2;            // 0..63
    const int acol = (tid & 3) << 2;      // 0,4,8,12
    const int brow = tid >> 5;            // 0..7
    const int bcol = (tid & 31) << 2;     // 0..124

    const float* Ap = X + (by * 128 + arow) * HID + acol;
    const float* Bp = W + brow * HID + bx * 128 + bcol;

    float acc[8][8];
#pragma unroll
    for (int i = 0; i < 8; i++)
#pragma unroll
        for (int j = 0; j < 8; j++) acc[i][j] = 0.0f;

    for (int k0 = 0; k0 < HID; k0 += 16) {
        float4 a0 = *(const float4*)(Ap + k0);
        float4 a1 = *(const float4*)(Ap + 64 * HID + k0);
        float4 b0 = *(const float4*)(Bp + (k0    ) * HID);
        float4 b1 = *(const float4*)(Bp + (k0 + 8) * HID);

        __syncthreads();
        As[(acol + 0) * 128 + arow] = a0.x;
        As[(acol + 1) * 128 + arow] = a0.y;
        As[(acol + 2) * 128 + arow] = a0.z;
        As[(acol + 3) * 128 + arow] = a0.w;
        As[(acol + 0) * 128 + arow + 64] = a1.x;
        As[(acol + 1) * 128 + arow + 64] = a1.y;
        As[(acol + 2) * 128 + arow + 64] = a1.z;
        As[(acol + 3) * 128 + arow + 64] = a1.w;
        *(float4*)(Bs + brow * 128 + bcol)       = b0;
        *(float4*)(Bs + (brow + 8) * 128 + bcol) = b1;
        __syncthreads();

#pragma unroll
        for (int k = 0; k < 16; k++) {
            float ar[8], br[8];
            *(float4*)(ar)     = *(const float4*)(As + k * 128 + ty * 8);
            *(float4*)(ar + 4) = *(const float4*)(As + k * 128 + ty * 8 + 4);
            *(float4*)(br)     = *(const float4*)(Bs + k * 128 + tx * 8);
            *(float4*)(br + 4) = *(const float4*)(Bs + k * 128 + tx * 8 + 4);
#pragma unroll
            for (int i = 0; i < 8; i++)
#pragma unroll
                for (int j = 0; j < 8; j++)
                    acc[i][j] += ar[i] * br[j];
        }
    }

    const int nbase = bx * 128 + tx * 8;
    float bb[8];
#pragma unroll
    for (int j = 0; j < 8; j++) bb[j] = bias[nbase + j];
    const int hh = nbase >> 6;
    const int d0 = nbase & 63;

#pragma unroll
    for (int i = 0; i < 8; i++) {
        int m  = by * 128 + ty * 8 + i;
        int bi = m >> 11;
        int s  = m & 2047;
        float* op = out + (((bi * NHEADS + hh) * S_LEN + s) * HD + d0);
        float4 r;
        r.x = acc[i][0] + bb[0]; r.y = acc[i][1] + bb[1];
        r.z = acc[i][2] + bb[2]; r.w = acc[i][3] + bb[3];
        *(float4*)(op) = r;
        r.x = acc[i][4] + bb[4]; r.y = acc[i][5] + bb[5];
        r.z = acc[i][6] + bb[6]; r.w = acc[i][7] + bb[7];
        *(float4*)(op + 4) = r;
    }
}

// ---------------------------------------------------------------------------
// Kernel B v2: block-sparse attention, 4 threads per query (16 dims each).
// 512 threads/CTA -> 16 warps/SM (was 4). Score = group butterfly-shuffle of
// 16-dim partial dots; softmax state (mx,l) replicated identically across the
// 4-lane group (bit-deterministic). Same sparsity structure:
//   query i = 128t + a: self key i, diag block (c<a), prev block (c>=a),
//   plus one strided key per earlier block (row 128m + a).
// ---------------------------------------------------------------------------

// Per-key processing for the 4-thread-per-query layout.
// KP/VP point at this thread's 16-dim slice of the key/value row.
#define PROC4(KP, VP, AMJ) do {                                               \
    const float4* kk4 = (const float4*)(KP);                                  \
    float s0 = 0.f, s1 = 0.f, s2 = 0.f, s3 = 0.f;                             \
    _Pragma("unroll")                                                         \
    for (int j = 0; j < 4; j++) {                                             \
        float4 kk = kk4[j];                                                   \
        s0 += q[4*j+0] * kk.x; s1 += q[4*j+1] * kk.y;                         \
        s2 += q[4*j+2] * kk.z; s3 += q[4*j+3] * kk.w;                         \
    }                                                                         \
    float s = (s0 + s1) + (s2 + s3);                                          \
    s += __shfl_xor_sync(gmask, s, 1);                                        \
    s += __shfl_xor_sync(gmask, s, 2);                                        \
    s = s * 0.125f + (AMJ);                                                   \
    if (s > mx) {                                                             \
        float corr = __expf(mx - s);                                          \
        l *= corr;                                                            \
        _Pragma("unroll")                                                     \
        for (int d = 0; d < 16; d++) ctx[d] *= corr;                          \
        mx = s;                                                               \
    }                                                                         \
    float p = __expf(s - mx);                                                 \
    l += p;                                                                   \
    const float4* vv4 = (const float4*)(VP);                                  \
    _Pragma("unroll")                                                         \
    for (int j = 0; j < 4; j++) {                                             \
        float4 vv = vv4[j];                                                   \
        ctx[4*j+0] += p * vv.x; ctx[4*j+1] += p * vv.y;                       \
        ctx[4*j+2] += p * vv.z; ctx[4*j+3] += p * vv.w;                       \
    }                                                                         \
} while (0)

__global__ __launch_bounds__(512)
void attn_kernel(const float* __restrict__ AM, float* __restrict__ Out) {
    extern __shared__ float sm[];
    float* kd  = sm;                // diag keys   [128][64]
    float* vd  = sm + 8192;         // diag values
    float* kp  = sm + 16384;        // prev keys
    float* vp  = sm + 24576;        // prev values
    float* ams = sm + 32768;        // [0,128) diag mask row, [128,256) prev

    const int t = blockIdx.x, h = blockIdx.y, b = blockIdx.z;
    const int tid  = threadIdx.x;
    const int a    = tid >> 2;          // query within tile (0..127)
    const int half = tid & 3;           // 16-dim slice (0..3)
    const int i    = t * 128 + a;       // global query row
    const int lane = tid & 31;
    const unsigned gmask = 0xFu << (lane & 28);  // this thread's 4-lane group

    const float* Qbh = g_q + ((b * NHEADS + h) * S_LEN) * HD;
    const float* Vbh = g_v + ((b * NHEADS + h) * S_LEN) * HD;
    const float* am  = AM + b * S_LEN;

    // Cooperative stage of diag (+ prev) K/V tiles: coalesced float4.
    {
        const float4* sk = (const float4*)(Qbh + t * 128 * HD);
        const float4* sv = (const float4*)(Vbh + t * 128 * HD);
        float4* dk = (float4*)kd;
        float4* dv = (float4*)vd;
#pragma unroll
        for (int it = 0; it < 4; it++) {
            int x = it * 512 + tid;
            dk[x] = sk[x];
            dv[x] = sv[x];
        }
        if (t > 0) {
            const float4* sk2 = (const float4*)(Qbh + (t - 1) * 128 * HD);
            const float4* sv2 = (const float4*)(Vbh + (t - 1) * 128 * HD);
            float4* dk2 = (float4*)kp;
            float4* dv2 = (float4*)vp;
#pragma unroll
            for (int it = 0; it < 4; it++) {
                int x = it * 512 + tid;
                dk2[x] = sk2[x];
                dv2[x] = sv2[x];
            }
        }
        // Stage attention-mask rows used by the fused loop.
        if (tid < 128)      ams[tid] = am[t * 128 + tid];
        else if (tid < 256) ams[tid] = (t > 0) ? am[(t - 1) * 128 + (tid - 128)] : 0.0f;
    }

    // Load this thread's 16-dim slice of q and self-v from global.
    float q[16], ctx[16];
    {
        const float4* qg = (const float4*)(Qbh + i * HD + half * 16);
        const float4* vg = (const float4*)(Vbh + i * HD + half * 16);
#pragma unroll
        for (int j = 0; j < 4; j++) {
            float4 f = qg[j];
            q[4*j+0] = f.x; q[4*j+1] = f.y; q[4*j+2] = f.z; q[4*j+3] = f.w;
            float4 g = vg[j];
            ctx[4*j+0] = g.x; ctx[4*j+1] = g.y; ctx[4*j+2] = g.z; ctx[4*j+3] = g.w;
        }
    }

    // Self key first: seeds max high, making the rescale branch rare.
    float mx, l;
    {
        float s0 = 0.f, s1 = 0.f, s2 = 0.f, s3 = 0.f;
#pragma unroll
        for (int j = 0; j < 4; j++) {
            s0 += q[4*j+0] * q[4*j+0]; s1 += q[4*j+1] * q[4*j+1];
            s2 += q[4*j+2] * q[4*j+2]; s3 += q[4*j+3] * q[4*j+3];
        }
        float s = (s0 + s1) + (s2 + s3);
        s += __shfl_xor_sync(gmask, s, 1);
        s += __shfl_xor_sync(gmask, s, 2);
        mx = s * 0.125f + am[i];
        l = 1.0f;                  // p_self = 1, ctx already = v_self
    }

    __syncthreads();

    // Fused diag/prev loop: key c from diag block when c < a, from prev block
    // when c >= a (t > 0). Complementary -> full lane utilization for t > 0.
    // The 4-lane group shares `a`, so activity & branches are group-coherent;
    // shuffles use the group mask and are safe under the t==0 divergence.
    const int slice = half * 16;
    for (int c = 0; c < 128; c++) {
        bool isdiag = (c < a);
        bool active = isdiag || (t > 0);
        if (active) {
            const float* kbp = (isdiag ? kd : kp) + c * HD + slice;
            const float* vbp = (isdiag ? vd : vp) + c * HD + slice;
            float amj = isdiag ? ams[c] : ams[128 + c];
            PROC4(kbp, vbp, amj);
        }
    }

    // Strided keys: one per earlier block, row 128*m + a (L2-resident gather).
    for (int mm = 0; mm + 1 < t; mm++) {
        int r = mm * 128 + a;
        PROC4(Qbh + r * HD + slice, Vbh + r * HD + slice, am[r]);
    }

    // Normalize and write out[b, i, h*64 + half*16 + d]
    float inv = 1.0f / l;
    float4* og = (float4*)(Out + (b * S_LEN + i) * (NHEADS * HD) + h * HD + slice);
#pragma unroll
    for (int j = 0; j < 4; j++) {
        float4 o;
        o.x = ctx[4*j+0] * inv; o.y = ctx[4*j+1] * inv;
        o.z = ctx[4*j+2] * inv; o.w = ctx[4*j+3] * inv;
        og[j] = o;
    }
}

// ---------------------------------------------------------------------------
extern "C" void kernel_launch(void* const* d_in, const int* in_sizes, int n_in,
                              void* d_out, int out_size) {
    const float* X  = (const float*)d_in[0];
    const float* AM = (const float*)d_in[1];
    const float* Wq = (const float*)d_in[2];
    const float* bq = (const float*)d_in[3];
    const float* Wv = (const float*)d_in[4];
    const float* bv = (const float*)d_in[5];
    float* out = (float*)d_out;

    // 4 KV tiles (128 KB) + 256 mask floats (1 KB)
    cudaFuncSetAttribute(attn_kernel,
                         cudaFuncAttributeMaxDynamicSharedMemorySize, 132096);

    qv_gemm<<<dim3(8, 32, 2), 256>>>(X, Wq, bq, Wv, bv);
    attn_kernel<<<dim3(16, NHEADS, BATCH), 512, 132096>>>(AM, out);
}

// round 7
// speedup vs baseline: 1.6314x; 1.6314x over previous
#include <cuda_runtime.h>
#include <cuda_bf16.h>
#include <cstdint>

#define S_LEN   2048
#define NHEADS  16
#define HD      64
#define BATCH   2
#define HID     1024

// Scratch: Q and V in head-major layout [B, H, S, 64]
__device__ float g_q[BATCH * NHEADS * S_LEN * HD];
__device__ float g_v[BATCH * NHEADS * S_LEN * HD];

// bf16 split operands for the tensor-core GEMM
__device__ __nv_bfloat16 g_xhi[4096 * 1024];
__device__ __nv_bfloat16 g_xlo[4096 * 1024];
__device__ __nv_bfloat16 g_wthi[2 * 1024 * 1024];   // W^T, [n][k]
__device__ __nv_bfloat16 g_wtlo[2 * 1024 * 1024];

// ---------------------------------------------------------------------------
// Arch-agnostic PTX helpers (sm_80-era: valid under compute_103 virtual arch)
// ---------------------------------------------------------------------------
__device__ __forceinline__ uint32_t smem_u32(const void* p) {
    uint32_t a;
    asm("{ .reg .u64 t; cvta.to.shared.u64 t, %1; cvt.u32.u64 %0, t; }"
        : "=r"(a) : "l"(p));
    return a;
}
__device__ __forceinline__ void cp16(uint32_t dst, const void* src) {
    asm volatile("cp.async.cg.shared.global [%0], [%1], 16;"
                 :: "r"(dst), "l"(src) : "memory");
}
#define CP_COMMIT() asm volatile("cp.async.commit_group;" ::: "memory")
#define CP_WAIT1()  asm volatile("cp.async.wait_group 1;" ::: "memory")
#define CP_WAIT0()  asm volatile("cp.async.wait_group 0;" ::: "memory")

#define LDSM4(r0, r1, r2, r3, addr)                                           \
    asm volatile("ldmatrix.sync.aligned.m8n8.x4.shared.b16 {%0,%1,%2,%3}, [%4];" \
                 : "=r"(r0), "=r"(r1), "=r"(r2), "=r"(r3) : "r"(addr))

#define MMA16816(d, a, b)                                                     \
    asm volatile("mma.sync.aligned.m16n8k16.row.col.f32.bf16.bf16.f32 "       \
                 "{%0,%1,%2,%3}, {%4,%5,%6,%7}, {%8,%9}, {%0,%1,%2,%3};"      \
                 : "+f"((d)[0]), "+f"((d)[1]), "+f"((d)[2]), "+f"((d)[3])     \
                 : "r"((a)[0]), "r"((a)[1]), "r"((a)[2]), "r"((a)[3]),        \
                   "r"((b)[0]), "r"((b)[1]))

// ---------------------------------------------------------------------------
// Prep 1: X fp32 -> (hi, lo) bf16 split, same [4096][1024] layout.
// ---------------------------------------------------------------------------
__global__ void split_x(const float* __restrict__ X) {
    int idx = blockIdx.x * blockDim.x + threadIdx.x;
    for (int i = idx; i < 4096 * 1024; i += gridDim.x * blockDim.x) {
        float x = X[i];
        __nv_bfloat16 hi = __float2bfloat16(x);
        g_xhi[i] = hi;
        g_xlo[i] = __float2bfloat16(x - __bfloat162float(hi));
    }
}

// ---------------------------------------------------------------------------
// Prep 2: W fp32 [k][n] -> W^T (hi, lo) bf16 [n][k]; smem tile transpose.
// ---------------------------------------------------------------------------
__global__ void split_w(const float* __restrict__ Wq, const float* __restrict__ Wv) {
    __shared__ float t[32][33];
    const int z = blockIdx.z;
    const float* W = z ? Wv : Wq;
    __nv_bfloat16* hi = g_wthi + (size_t)z * 1024 * 1024;
    __nv_bfloat16* lo = g_wtlo + (size_t)z * 1024 * 1024;
    const int k0 = blockIdx.y * 32, n0 = blockIdx.x * 32;
    const int tx = threadIdx.x, ty = threadIdx.y;    // 32 x 8
#pragma unroll
    for (int j = 0; j < 32; j += 8)
        t[ty + j][tx] = W[(size_t)(k0 + ty + j) * 1024 + n0 + tx];
    __syncthreads();
#pragma unroll
    for (int j = 0; j < 32; j += 8) {
        float x = t[tx][ty + j];                     // W[k0+tx][n0+ty+j]
        __nv_bfloat16 h = __float2bfloat16(x);
        size_t o = (size_t)(n0 + ty + j) * 1024 + k0 + tx;
        hi[o] = h;
        lo[o] = __float2bfloat16(x - __bfloat162float(h));
    }
}

// ---------------------------------------------------------------------------
// Kernel A v3: bf16-split GEMM via mma.sync (HMMA) — compute_103-legal.
// Y = X @ W + b as D = A'.B'^T, K' = 3*1024 segments:
//   seg0: Xhi.Wt_hi, seg1: Xlo.Wt_hi, seg2: Xhi.Wt_lo  (lo.lo dropped)
// 128x128 tile, BK=32, 8 warps (4m x 2n), warp tile 32x64, fp32 reg accum.
// cp.async double-buffered smem; 16B-chunk XOR swizzle; ldmatrix fragments.
// ---------------------------------------------------------------------------
__global__ __launch_bounds__(256)
void qv_gemm_mma(const float* __restrict__ bq, const float* __restrict__ bv) {
    __shared__ __align__(16) __nv_bfloat16 sA[2][128 * 32];
    __shared__ __align__(16) __nv_bfloat16 sB[2][128 * 32];

    const int tid = threadIdx.x, lane = tid & 31, wid = tid >> 5;
    const int wm = wid & 3, wn = wid >> 2;        // 4 x 2 warp grid
    const int bx = blockIdx.x, by = blockIdx.y, z = blockIdx.z;
    const int m0 = by * 128, n0 = bx * 128;

    const __nv_bfloat16* wt_hi = g_wthi + (size_t)z * 1024 * 1024;
    const __nv_bfloat16* wt_lo = g_wtlo + (size_t)z * 1024 * 1024;

    const uint32_t sAu = smem_u32(sA);
    const uint32_t sBu = smem_u32(sB);

    float acc[2][8][4];
#pragma unroll
    for (int i = 0; i < 2; i++)
#pragma unroll
        for (int j = 0; j < 8; j++)
#pragma unroll
            for (int r = 0; r < 4; r++) acc[i][j][r] = 0.0f;

    // --- prefetch lambda: chunk c (of 96) into buffer buf ---
    const int pr  = tid >> 2;          // 0..63 (two row passes)
    const int pcc = tid & 3;           // 16B chunk within 64B row
    auto prefetch = [&](int c, int buf) {
        const int seg = c >> 5;
        const int kk = (c & 31) * 32;
        const __nv_bfloat16* As = (seg == 1) ? g_xlo : g_xhi;
        const __nv_bfloat16* Bs = (seg == 2) ? wt_lo : wt_hi;
#pragma unroll
        for (int p = 0; p < 2; p++) {
            int row = pr + p * 64;
            uint32_t sw = row * 64 + ((pcc ^ (row & 3)) << 4);
            cp16(sAu + buf * 8192 + sw,
                 As + (size_t)(m0 + row) * 1024 + kk + pcc * 8);
            cp16(sBu + buf * 8192 + sw,
                 Bs + (size_t)(n0 + row) * 1024 + kk + pcc * 8);
        }
    };

    // ldmatrix per-lane row indices (fixed across chunks)
    const int rowA  = wm * 32 + (lane & 15);          // + mt*16
    const int kselA = lane >> 4;                      // k-half chunk for A
    const int rowB  = wn * 64 + ((lane >> 4) & 1) * 8 + (lane & 7);  // + jj*16
    const int kselB = (lane >> 3) & 1;

    prefetch(0, 0);
    CP_COMMIT();

    for (int c = 0; c < 96; c++) {
        if (c + 1 < 96) { prefetch(c + 1, (c + 1) & 1); CP_COMMIT(); CP_WAIT1(); }
        else            { CP_WAIT0(); }
        __syncthreads();

        const uint32_t abase = sAu + (c & 1) * 8192;
        const uint32_t bbase = sBu + (c & 1) * 8192;

#pragma unroll
        for (int ks = 0; ks < 2; ks++) {
            uint32_t a[2][4];
#pragma unroll
            for (int mt = 0; mt < 2; mt++) {
                int row = rowA + mt * 16;
                uint32_t addr = abase + row * 64
                              + (((ks * 2 + kselA) ^ (row & 3)) << 4);
                LDSM4(a[mt][0], a[mt][1], a[mt][2], a[mt][3], addr);
            }
            uint32_t b[8][2];
#pragma unroll
            for (int jj = 0; jj < 4; jj++) {
                int row = rowB + jj * 16;
                uint32_t addr = bbase + row * 64
                              + (((ks * 2 + kselB) ^ (row & 3)) << 4);
                uint32_t r0, r1, r2, r3;
                LDSM4(r0, r1, r2, r3, addr);
                b[2*jj][0]   = r0; b[2*jj][1]   = r1;
                b[2*jj+1][0] = r2; b[2*jj+1][1] = r3;
            }
#pragma unroll
            for (int i = 0; i < 2; i++)
#pragma unroll
                for (int j = 0; j < 8; j++)
                    MMA16816(acc[i][j], a[i], b[j]);
        }
        __syncthreads();
    }

    // --- epilogue: bias add, scatter to head-major [B,H,S,64] ---
    const float* bias = z ? bv : bq;
    float* out = z ? g_v : g_q;
    const int gr = lane >> 2, tc = lane & 3;
    const int h = bx * 2 + wn;                // warp's 64-col span = one head
    const int nbb = bx * 128 + wn * 64;

#pragma unroll
    for (int i = 0; i < 2; i++) {
        int m = m0 + wm * 32 + i * 16 + gr;
        int bi = m >> 11, s = m & 2047;
        float* orow = out + (((size_t)bi * NHEADS + h) * S_LEN + s) * HD;
#pragma unroll
        for (int j = 0; j < 8; j++) {
            int d = j * 8 + tc * 2;
            float b0 = bias[nbb + d], b1 = bias[nbb + d + 1];
            float2 v0 = { acc[i][j][0] + b0, acc[i][j][1] + b1 };
            float2 v1 = { acc[i][j][2] + b0, acc[i][j][3] + b1 };
            *(float2*)(orow + d)          = v0;   // row m
            *(float2*)(orow + 8 * HD + d) = v1;   // row m+8
        }
    }
}

// ---------------------------------------------------------------------------
// Kernel B: block-sparse attention (proven R1 version, 230us).
// ---------------------------------------------------------------------------
#define PROC_KEY(KP, VP, AMJ) do {                                            \
    float s0 = 0.f, s1 = 0.f, s2 = 0.f, s3 = 0.f;                             \
    const float4* kk4 = (const float4*)(KP);                                  \
    _Pragma("unroll")                                                         \
    for (int d4 = 0; d4 < 16; d4++) {                                         \
        float4 kk = kk4[d4];                                                  \
        s0 += q[d4*4+0] * kk.x; s1 += q[d4*4+1] * kk.y;                       \
        s2 += q[d4*4+2] * kk.z; s3 += q[d4*4+3] * kk.w;                       \
    }                                                                         \
    float s = ((s0 + s1) + (s2 + s3)) * 0.125f + (AMJ);                       \
    if (s > mx) {                                                             \
        float corr = __expf(mx - s);                                          \
        l *= corr;                                                            \
        _Pragma("unroll")                                                     \
        for (int d = 0; d < 64; d++) ctx[d] *= corr;                          \
        mx = s;                                                               \
    }                                                                         \
    float p = __expf(s - mx);                                                 \
    l += p;                                                                   \
    const float4* vv4 = (const float4*)(VP);                                  \
    _Pragma("unroll")                                                         \
    for (int d4 = 0; d4 < 16; d4++) {                                         \
        float4 vv = vv4[d4];                                                  \
        ctx[d4*4+0] += p * vv.x; ctx[d4*4+1] += p * vv.y;                     \
        ctx[d4*4+2] += p * vv.z; ctx[d4*4+3] += p * vv.w;                     \
    }                                                                         \
} while (0)

__global__ __launch_bounds__(128)
void attn_kernel(const float* __restrict__ AM, float* __restrict__ Out) {
    extern __shared__ float sm[];
    float* kd = sm;                // diag keys   [128][64]
    float* vd = sm + 8192;         // diag values
    float* kp = sm + 16384;        // prev keys
    float* vp = sm + 24576;        // prev values

    const int t = blockIdx.x, h = blockIdx.y, b = blockIdx.z;
    const int a = threadIdx.x;
    const int i = t * 128 + a;

    const float* Qbh = g_q + ((b * NHEADS + h) * S_LEN) * HD;
    const float* Vbh = g_v + ((b * NHEADS + h) * S_LEN) * HD;
    const float* am  = AM + b * S_LEN;

    {
        const float4* sk = (const float4*)(Qbh + t * 128 * HD);
        const float4* sv = (const float4*)(Vbh + t * 128 * HD);
        float4* dk = (float4*)kd;
        float4* dv = (float4*)vd;
#pragma unroll
        for (int it = 0; it < 16; it++) {
            int x = it * 128 + a;
            dk[x] = sk[x];
            dv[x] = sv[x];
        }
        if (t > 0) {
            const float4* sk2 = (const float4*)(Qbh + (t - 1) * 128 * HD);
            const float4* sv2 = (const float4*)(Vbh + (t - 1) * 128 * HD);
            float4* dk2 = (float4*)kp;
            float4* dv2 = (float4*)vp;
#pragma unroll
            for (int it = 0; it < 16; it++) {
                int x = it * 128 + a;
                dk2[x] = sk2[x];
                dv2[x] = sv2[x];
            }
        }
    }

    float q[64], ctx[64];
    {
        const float4* qg = (const float4*)(Qbh + i * HD);
        const float4* vg = (const float4*)(Vbh + i * HD);
#pragma unroll
        for (int d4 = 0; d4 < 16; d4++) {
            float4 f = qg[d4];
            q[d4*4+0] = f.x; q[d4*4+1] = f.y; q[d4*4+2] = f.z; q[d4*4+3] = f.w;
            float4 g = vg[d4];
            ctx[d4*4+0] = g.x; ctx[d4*4+1] = g.y; ctx[d4*4+2] = g.z; ctx[d4*4+3] = g.w;
        }
    }

    float mx, l;
    {
        float s0 = 0.f, s1 = 0.f, s2 = 0.f, s3 = 0.f;
#pragma unroll
        for (int d = 0; d < 64; d += 4) {
            s0 += q[d] * q[d];     s1 += q[d+1] * q[d+1];
            s2 += q[d+2] * q[d+2]; s3 += q[d+3] * q[d+3];
        }
        mx = ((s0 + s1) + (s2 + s3)) * 0.125f + am[i];
        l = 1.0f;
    }

    __syncthreads();

    for (int c = 0; c < 128; c++) {
        bool isdiag = (c < a);
        bool active = isdiag || (t > 0);
        if (active) {
            const float* kbp = isdiag ? (kd + c * HD) : (kp + c * HD);
            const float* vbp = isdiag ? (vd + c * HD) : (vp + c * HD);
            int jrow = isdiag ? (t * 128 + c) : ((t - 1) * 128 + c);
            PROC_KEY(kbp, vbp, am[jrow]);
        }
    }

    for (int mm = 0; mm + 1 < t; mm++) {
        int r = mm * 128 + a;
        PROC_KEY(Qbh + r * HD, Vbh + r * HD, am[r]);
    }

    float inv = 1.0f / l;
    float4* og = (float4*)(Out + (b * S_LEN + i) * (NHEADS * HD) + h * HD);
#pragma unroll
    for (int d4 = 0; d4 < 16; d4++) {
        float4 o;
        o.x = ctx[d4*4+0] * inv; o.y = ctx[d4*4+1] * inv;
        o.z = ctx[d4*4+2] * inv; o.w = ctx[d4*4+3] * inv;
        og[d4] = o;
    }
}

// ---------------------------------------------------------------------------
extern "C" void kernel_launch(void* const* d_in, const int* in_sizes, int n_in,
                              void* d_out, int out_size) {
    const float* X  = (const float*)d_in[0];
    const float* AM = (const float*)d_in[1];
    const float* Wq = (const float*)d_in[2];
    const float* bq = (const float*)d_in[3];
    const float* Wv = (const float*)d_in[4];
    const float* bv = (const float*)d_in[5];
    float* out = (float*)d_out;

    cudaFuncSetAttribute(attn_kernel,
                         cudaFuncAttributeMaxDynamicSharedMemorySize, 131072);

    split_x<<<4096, 256>>>(X);
    split_w<<<dim3(32, 32, 2), dim3(32, 8)>>>(Wq, Wv);
    qv_gemm_mma<<<dim3(8, 32, 2), 256>>>(bq, bv);
    attn_kernel<<<dim3(16, NHEADS, BATCH), 128, 131072>>>(AM, out);
}

// round 14
// speedup vs baseline: 1.6860x; 1.0335x over previous
#include <cuda_runtime.h>
#include <cuda_bf16.h>
#include <cstdint>

#define S_LEN   2048
#define NHEADS  16
#define HD      64
#define BATCH   2
#define HID     1024

// Scratch: Q and V in head-major layout [B, H, S, 64]
__device__ float g_q[BATCH * NHEADS * S_LEN * HD];
__device__ float g_v[BATCH * NHEADS * S_LEN * HD];

// bf16 split operands for the tensor-core GEMM
__device__ __nv_bfloat16 g_xhi[4096 * 1024];
__device__ __nv_bfloat16 g_xlo[4096 * 1024];
__device__ __nv_bfloat16 g_wthi[2 * 1024 * 1024];   // W^T, [n][k]
__device__ __nv_bfloat16 g_wtlo[2 * 1024 * 1024];

// ---------------------------------------------------------------------------
// Arch-agnostic PTX helpers (sm_80-era: valid under compute_103 virtual arch)
// ---------------------------------------------------------------------------
__device__ __forceinline__ uint32_t smem_u32(const void* p) {
    uint32_t a;
    asm("{ .reg .u64 t; cvta.to.shared.u64 t, %1; cvt.u32.u64 %0, t; }"
        : "=r"(a) : "l"(p));
    return a;
}
__device__ __forceinline__ void cp16(uint32_t dst, const void* src) {
    asm volatile("cp.async.cg.shared.global [%0], [%1], 16;"
                 :: "r"(dst), "l"(src) : "memory");
}
#define CP_COMMIT() asm volatile("cp.async.commit_group;" ::: "memory")
#define CP_WAIT1()  asm volatile("cp.async.wait_group 1;" ::: "memory")
#define CP_WAIT0()  asm volatile("cp.async.wait_group 0;" ::: "memory")

#define LDSM4(r0, r1, r2, r3, addr)                                           \
    asm volatile("ldmatrix.sync.aligned.m8n8.x4.shared.b16 {%0,%1,%2,%3}, [%4];" \
                 : "=r"(r0), "=r"(r1), "=r"(r2), "=r"(r3) : "r"(addr))

#define MMA16816(d, a, b)                                                     \
    asm volatile("mma.sync.aligned.m16n8k16.row.col.f32.bf16.bf16.f32 "       \
                 "{%0,%1,%2,%3}, {%4,%5,%6,%7}, {%8,%9}, {%0,%1,%2,%3};"      \
                 : "+f"((d)[0]), "+f"((d)[1]), "+f"((d)[2]), "+f"((d)[3])     \
                 : "r"((a)[0]), "r"((a)[1]), "r"((a)[2]), "r"((a)[3]),        \
                   "r"((b)[0]), "r"((b)[1]))

// ---------------------------------------------------------------------------
// Prep 1: X fp32 -> (hi, lo) bf16 split, same [4096][1024] layout.
// ---------------------------------------------------------------------------
__global__ void split_x(const float* __restrict__ X) {
    int idx = blockIdx.x * blockDim.x + threadIdx.x;
    for (int i = idx; i < 4096 * 1024; i += gridDim.x * blockDim.x) {
        float x = X[i];
        __nv_bfloat16 hi = __float2bfloat16(x);
        g_xhi[i] = hi;
        g_xlo[i] = __float2bfloat16(x - __bfloat162float(hi));
    }
}

// ---------------------------------------------------------------------------
// Prep 2: W fp32 [k][n] -> W^T (hi, lo) bf16 [n][k]; smem tile transpose.
// ---------------------------------------------------------------------------
__global__ void split_w(const float* __restrict__ Wq, const float* __restrict__ Wv) {
    __shared__ float t[32][33];
    const int z = blockIdx.z;
    const float* W = z ? Wv : Wq;
    __nv_bfloat16* hi = g_wthi + (size_t)z * 1024 * 1024;
    __nv_bfloat16* lo = g_wtlo + (size_t)z * 1024 * 1024;
    const int k0 = blockIdx.y * 32, n0 = blockIdx.x * 32;
    const int tx = threadIdx.x, ty = threadIdx.y;    // 32 x 8
#pragma unroll
    for (int j = 0; j < 32; j += 8)
        t[ty + j][tx] = W[(size_t)(k0 + ty + j) * 1024 + n0 + tx];
    __syncthreads();
#pragma unroll
    for (int j = 0; j < 32; j += 8) {
        float x = t[tx][ty + j];                     // W[k0+tx][n0+ty+j]
        __nv_bfloat16 h = __float2bfloat16(x);
        size_t o = (size_t)(n0 + ty + j) * 1024 + k0 + tx;
        hi[o] = h;
        lo[o] = __float2bfloat16(x - __bfloat162float(h));
    }
}

// ---------------------------------------------------------------------------
// Kernel A v3: bf16-split GEMM via mma.sync (HMMA) — proven R6 version.
// ---------------------------------------------------------------------------
__global__ __launch_bounds__(256)
void qv_gemm_mma(const float* __restrict__ bq, const float* __restrict__ bv) {
    __shared__ __align__(16) __nv_bfloat16 sA[2][128 * 32];
    __shared__ __align__(16) __nv_bfloat16 sB[2][128 * 32];

    const int tid = threadIdx.x, lane = tid & 31, wid = tid >> 5;
    const int wm = wid & 3, wn = wid >> 2;        // 4 x 2 warp grid
    const int bx = blockIdx.x, by = blockIdx.y, z = blockIdx.z;
    const int m0 = by * 128, n0 = bx * 128;

    const __nv_bfloat16* wt_hi = g_wthi + (size_t)z * 1024 * 1024;
    const __nv_bfloat16* wt_lo = g_wtlo + (size_t)z * 1024 * 1024;

    const uint32_t sAu = smem_u32(sA);
    const uint32_t sBu = smem_u32(sB);

    float acc[2][8][4];
#pragma unroll
    for (int i = 0; i < 2; i++)
#pragma unroll
        for (int j = 0; j < 8; j++)
#pragma unroll
            for (int r = 0; r < 4; r++) acc[i][j][r] = 0.0f;

    const int pr  = tid >> 2;          // 0..63 (two row passes)
    const int pcc = tid & 3;           // 16B chunk within 64B row
    auto prefetch = [&](int c, int buf) {
        const int seg = c >> 5;
        const int kk = (c & 31) * 32;
        const __nv_bfloat16* As = (seg == 1) ? g_xlo : g_xhi;
        const __nv_bfloat16* Bs = (seg == 2) ? wt_lo : wt_hi;
#pragma unroll
        for (int p = 0; p < 2; p++) {
            int row = pr + p * 64;
            uint32_t sw = row * 64 + ((pcc ^ (row & 3)) << 4);
            cp16(sAu + buf * 8192 + sw,
                 As + (size_t)(m0 + row) * 1024 + kk + pcc * 8);
            cp16(sBu + buf * 8192 + sw,
                 Bs + (size_t)(n0 + row) * 1024 + kk + pcc * 8);
        }
    };

    const int rowA  = wm * 32 + (lane & 15);
    const int kselA = lane >> 4;
    const int rowB  = wn * 64 + ((lane >> 4) & 1) * 8 + (lane & 7);
    const int kselB = (lane >> 3) & 1;

    prefetch(0, 0);
    CP_COMMIT();

    for (int c = 0; c < 96; c++) {
        if (c + 1 < 96) { prefetch(c + 1, (c + 1) & 1); CP_COMMIT(); CP_WAIT1(); }
        else            { CP_WAIT0(); }
        __syncthreads();

        const uint32_t abase = sAu + (c & 1) * 8192;
        const uint32_t bbase = sBu + (c & 1) * 8192;

#pragma unroll
        for (int ks = 0; ks < 2; ks++) {
            uint32_t a[2][4];
#pragma unroll
            for (int mt = 0; mt < 2; mt++) {
                int row = rowA + mt * 16;
                uint32_t addr = abase + row * 64
                              + (((ks * 2 + kselA) ^ (row & 3)) << 4);
                LDSM4(a[mt][0], a[mt][1], a[mt][2], a[mt][3], addr);
            }
            uint32_t b[8][2];
#pragma unroll
            for (int jj = 0; jj < 4; jj++) {
                int row = rowB + jj * 16;
                uint32_t addr = bbase + row * 64
                              + (((ks * 2 + kselB) ^ (row & 3)) << 4);
                uint32_t r0, r1, r2, r3;
                LDSM4(r0, r1, r2, r3, addr);
                b[2*jj][0]   = r0; b[2*jj][1]   = r1;
                b[2*jj+1][0] = r2; b[2*jj+1][1] = r3;
            }
#pragma unroll
            for (int i = 0; i < 2; i++)
#pragma unroll
                for (int j = 0; j < 8; j++)
                    MMA16816(acc[i][j], a[i], b[j]);
        }
        __syncthreads();
    }

    const float* bias = z ? bv : bq;
    float* out = z ? g_v : g_q;
    const int gr = lane >> 2, tc = lane & 3;
    const int h = bx * 2 + wn;
    const int nbb = bx * 128 + wn * 64;

#pragma unroll
    for (int i = 0; i < 2; i++) {
        int m = m0 + wm * 32 + i * 16 + gr;
        int bi = m >> 11, s = m & 2047;
        float* orow = out + (((size_t)bi * NHEADS + h) * S_LEN + s) * HD;
#pragma unroll
        for (int j = 0; j < 8; j++) {
            int d = j * 8 + tc * 2;
            float b0 = bias[nbb + d], b1 = bias[nbb + d + 1];
            float2 v0 = { acc[i][j][0] + b0, acc[i][j][1] + b1 };
            float2 v1 = { acc[i][j][2] + b0, acc[i][j][3] + b1 };
            *(float2*)(orow + d)          = v0;
            *(float2*)(orow + 8 * HD + d) = v1;
        }
    }
}

// ---------------------------------------------------------------------------
// Kernel B v3.1: paired-tile block-sparse attention (BUGFIX: mask staging).
// One CTA = query tiles {t2, t2+1} (256 threads, 8 warps). They share key
// block t2, so smem holds 3 K + 3 V tiles (192 KB).
//   group A (tid<128): tile t2,   diag=block t2,   prev=block t2-1
//   group B (tid>=128): tile t2+1, diag=block t2+1, prev=block t2
// FIX vs v3: ams has 384 entries but only 256 threads — stage with a strided
// loop so ams[256..383] (group B's diag mask row) is actually written.
// ---------------------------------------------------------------------------
#define PROC_KEY(KP, VP, AMJ) do {                                            \
    float s0 = 0.f, s1 = 0.f, s2 = 0.f, s3 = 0.f;                             \
    const float4* kk4 = (const float4*)(KP);                                  \
    _Pragma("unroll")                                                         \
    for (int d4 = 0; d4 < 16; d4++) {                                         \
        float4 kk = kk4[d4];                                                  \
        s0 += q[d4*4+0] * kk.x; s1 += q[d4*4+1] * kk.y;                       \
        s2 += q[d4*4+2] * kk.z; s3 += q[d4*4+3] * kk.w;                       \
    }                                                                         \
    float s = ((s0 + s1) + (s2 + s3)) * 0.125f + (AMJ);                       \
    if (s > mx) {                                                             \
        float corr = __expf(mx - s);                                          \
        l *= corr;                                                            \
        _Pragma("unroll")                                                     \
        for (int d = 0; d < 64; d++) ctx[d] *= corr;                          \
        mx = s;                                                               \
    }                                                                         \
    float p = __expf(s - mx);                                                 \
    l += p;                                                                   \
    const float4* vv4 = (const float4*)(VP);                                  \
    _Pragma("unroll")                                                         \
    for (int d4 = 0; d4 < 16; d4++) {                                         \
        float4 vv = vv4[d4];                                                  \
        ctx[d4*4+0] += p * vv.x; ctx[d4*4+1] += p * vv.y;                     \
        ctx[d4*4+2] += p * vv.z; ctx[d4*4+3] += p * vv.w;                     \
    }                                                                         \
} while (0)

#define ATTN_SMEM (49536 * 4)   // 6 KV tiles (192 KB) + 384 mask floats

__global__ __launch_bounds__(256)
void attn_kernel(const float* __restrict__ AM, float* __restrict__ Out) {
    extern __shared__ float sm[];
    // blocks: P = t2-1, C = t2, N = t2+1
    float* kP = sm;             float* vP = sm + 8192;
    float* kC = sm + 16384;     float* vC = sm + 24576;
    float* kN = sm + 32768;     float* vN = sm + 40960;
    float* ams = sm + 49152;    // [P(128) | C(128) | N(128)]

    const int t2 = (7 - blockIdx.x) * 2;     // heavy tiles first in wave 1
    const int h = blockIdx.y, b = blockIdx.z;
    const int tid = threadIdx.x;
    const int grp = tid >> 7;                // 0: tile t2, 1: tile t2+1
    const int a = tid & 127;                 // query within tile
    const int t = t2 + grp;
    const int i = t * 128 + a;

    const float* Qbh = g_q + ((b * NHEADS + h) * S_LEN) * HD;
    const float* Vbh = g_v + ((b * NHEADS + h) * S_LEN) * HD;
    const float* am  = AM + b * S_LEN;

    // Cooperative stage: 3 K tiles + 3 V tiles, 256 threads, float4.
    {
        const float4* srcK = (const float4*)(Qbh + t2 * 128 * HD);   // C
        const float4* srcV = (const float4*)(Vbh + t2 * 128 * HD);
        float4* dC_k = (float4*)kC; float4* dC_v = (float4*)vC;
        float4* dN_k = (float4*)kN; float4* dN_v = (float4*)vN;
#pragma unroll
        for (int it = 0; it < 8; it++) {
            int x = it * 256 + tid;
            dC_k[x] = srcK[x];
            dC_v[x] = srcV[x];
            dN_k[x] = srcK[2048 + x];        // N = C + one tile
            dN_v[x] = srcV[2048 + x];
        }
        if (t2 > 0) {
            float4* dP_k = (float4*)kP; float4* dP_v = (float4*)vP;
#pragma unroll
            for (int it = 0; it < 8; it++) {
                int x = it * 256 + tid;
                dP_k[x] = srcK[x - 2048];    // P = C - one tile
                dP_v[x] = srcV[x - 2048];
            }
        }
        // FIX: 384 entries, 256 threads -> strided loop (v3 used `if (tid<384)`
        // which left ams[256..383] — group B's diag mask row — uninitialized).
#pragma unroll
        for (int x = tid; x < 384; x += 256) {
            int r = t2 * 128 - 128 + x;
            ams[x] = (r >= 0) ? am[r] : 0.0f;
        }
    }

    // Group pointers (R1 naming: kd/vd = diag block, kp/vp = prev block).
    const float* kd = grp ? kN : kC;
    const float* vd = grp ? vN : vC;
    const float* kp = grp ? kC : kP;
    const float* vp = grp ? vC : vP;
    const float* amd = ams + 128 + grp * 128;   // diag mask row
    const float* amp = ams + grp * 128;         // prev mask row

    // Load q and self-v from global.
    float q[64], ctx[64];
    {
        const float4* qg = (const float4*)(Qbh + i * HD);
        const float4* vg = (const float4*)(Vbh + i * HD);
#pragma unroll
        for (int d4 = 0; d4 < 16; d4++) {
            float4 f = qg[d4];
            q[d4*4+0] = f.x; q[d4*4+1] = f.y; q[d4*4+2] = f.z; q[d4*4+3] = f.w;
            float4 g = vg[d4];
            ctx[d4*4+0] = g.x; ctx[d4*4+1] = g.y; ctx[d4*4+2] = g.z; ctx[d4*4+3] = g.w;
        }
    }

    // Self key seeds the max (rescale branch stays rare).
    float mx, l;
    {
        float s0 = 0.f, s1 = 0.f, s2 = 0.f, s3 = 0.f;
#pragma unroll
        for (int d = 0; d < 64; d += 4) {
            s0 += q[d] * q[d];     s1 += q[d+1] * q[d+1];
            s2 += q[d+2] * q[d+2]; s3 += q[d+3] * q[d+3];
        }
        mx = ((s0 + s1) + (s2 + s3)) * 0.125f + am[i];
        l = 1.0f;
    }

    __syncthreads();

    // Fused diag/prev loop (identical shape to R1).
    for (int c = 0; c < 128; c++) {
        bool isdiag = (c < a);
        bool active = isdiag || (t > 0);
        if (active) {
            const float* kbp = isdiag ? (kd + c * HD) : (kp + c * HD);
            const float* vbp = isdiag ? (vd + c * HD) : (vp + c * HD);
            float amj = isdiag ? amd[c] : amp[c];
            PROC_KEY(kbp, vbp, amj);
        }
    }

    // Strided keys: one per earlier block, row 128*m + a (L2 gather).
    for (int mm = 0; mm + 1 < t; mm++) {
        int r = mm * 128 + a;
        PROC_KEY(Qbh + r * HD, Vbh + r * HD, am[r]);
    }

    // Normalize and write out[b, i, h*64 + d]
    float inv = 1.0f / l;
    float4* og = (float4*)(Out + (b * S_LEN + i) * (NHEADS * HD) + h * HD);
#pragma unroll
    for (int d4 = 0; d4 < 16; d4++) {
        float4 o;
        o.x = ctx[d4*4+0] * inv; o.y = ctx[d4*4+1] * inv;
        o.z = ctx[d4*4+2] * inv; o.w = ctx[d4*4+3] * inv;
        og[d4] = o;
    }
}

// ---------------------------------------------------------------------------
extern "C" void kernel_launch(void* const* d_in, const int* in_sizes, int n_in,
                              void* d_out, int out_size) {
    const float* X  = (const float*)d_in[0];
    const float* AM = (const float*)d_in[1];
    const float* Wq = (const float*)d_in[2];
    const float* bq = (const float*)d_in[3];
    const float* Wv = (const float*)d_in[4];
    const float* bv = (const float*)d_in[5];
    float* out = (float*)d_out;

    cudaFuncSetAttribute(attn_kernel,
                         cudaFuncAttributeMaxDynamicSharedMemorySize, ATTN_SMEM);

    split_x<<<4096, 256>>>(X);
    split_w<<<dim3(32, 32, 2), dim3(32, 8)>>>(Wq, Wv);
    qv_gemm_mma<<<dim3(8, 32, 2), 256>>>(bq, bv);
    attn_kernel<<<dim3(8, NHEADS, BATCH), 256, ATTN_SMEM>>>(AM, out);
}